// round 5
// baseline (speedup 1.0000x reference)
#include <cuda_runtime.h>
#include <cstdint>

// GTN collapses (softmax over singleton axis == 1 -> gtconv == 2*A):
//   H   = 4*(A@A) + I
//   inv = 2 / rowsum(H)   (guarded)
//   out = diag(inv) @ (H @ A)
// tcgen05 unavailable (harness targets plain sm_103). GEMMs run on int8 IMMA
// (mma.sync m16n8k32, exact s32 accumulation): 2x K-per-instruction vs bf16,
// quantization error averages over K=2048 -> rel err ~2e-4.

#define NMAT 2048
static constexpr int BM = 128;
static constexpr int BN = 128;
static constexpr int BK = 64;                    // 64 int8 = 64B rows
static constexpr int STAGES = 4;
static constexpr int KT = NMAT / BK;             // 32
static constexpr int STAGE_BYTES = BM * 64;      // 8KB
static constexpr int SMEM_B_OFF = STAGES * STAGE_BYTES;
static constexpr int SMEM_DYN = 2 * STAGES * STAGE_BYTES;    // 64KB

static constexpr float QA = 127.0f;              // A scale
static constexpr float SH = 127.0f / 2560.0f;    // H scale (|H|max ~2350 + margin)
static constexpr float SCALE1 = 4.0f / (QA * QA);        // acc -> H
static constexpr float SCALE2 = 1.0f / (SH * QA);        // acc -> H@A

__device__ char g_Aq[(size_t)NMAT * NMAT];
__device__ char g_ATq[(size_t)NMAT * NMAT];
__device__ char g_Hq[(size_t)NMAT * NMAT];
__device__ float g_rowpart[2][NMAT / BN][NMAT];
__device__ float g_inv[NMAT];

__device__ __forceinline__ uint32_t smem_u32(const void* p) {
    uint32_t a;
    asm("{ .reg .u64 t; cvta.to.shared.u64 t, %1; cvt.u32.u64 %0, t; }" : "=r"(a) : "l"(p));
    return a;
}
#define CP_ASYNC16(dst, src) asm volatile("cp.async.cg.shared.global [%0], [%1], 16;" :: "r"(dst), "l"(src) : "memory")
#define CP_COMMIT()          asm volatile("cp.async.commit_group;" ::: "memory")
#define CP_WAIT2()           asm volatile("cp.async.wait_group 2;" ::: "memory")
#define LDSM_X4(r0, r1, r2, r3, a) \
    asm volatile("ldmatrix.sync.aligned.m8n8.x4.shared.b16 {%0,%1,%2,%3}, [%4];" \
                 : "=r"(r0), "=r"(r1), "=r"(r2), "=r"(r3) : "r"(a))
#define MMA_S8(c, a, b) \
    asm volatile("mma.sync.aligned.m16n8k32.row.col.s32.s8.s8.s32 " \
                 "{%0,%1,%2,%3}, {%4,%5,%6,%7}, {%8,%9}, {%0,%1,%2,%3};" \
                 : "+r"((c)[0]), "+r"((c)[1]), "+r"((c)[2]), "+r"((c)[3]) \
                 : "r"((a)[0]), "r"((a)[1]), "r"((a)[2]), "r"((a)[3]), "r"((b)[0]), "r"((b)[1]))

__device__ __forceinline__ uint32_t swz(int row, int colb) {
    return (uint32_t)(row * 64 + (colb ^ (((row >> 1) & 3) << 4)));
}
__device__ __forceinline__ char q8(float v, float s) {
    int q = __float2int_rn(v * s);
    q = max(-127, min(127, q));
    return (char)q;
}

// ---------------- A -> int8 (row-major and transposed) ----------------
__global__ void convert_kernel(const float* __restrict__ A)
{
    __shared__ float t[32][33];
    const int tx = threadIdx.x, ty = threadIdx.y;
    const int x = blockIdx.x * 32 + tx;
    const int y0 = blockIdx.y * 32;
#pragma unroll
    for (int j = 0; j < 32; j += 8) {
        const int row = y0 + j + ty;
        const float v = A[(size_t)row * NMAT + x];
        t[j + ty][tx] = v;
        g_Aq[(size_t)row * NMAT + x] = q8(v, QA);
    }
    __syncthreads();
    const int nx = y0 + tx;
#pragma unroll
    for (int j = 0; j < 32; j += 8) {
        const int orow = blockIdx.x * 32 + j + ty;
        g_ATq[(size_t)orow * NMAT + nx] = q8(t[tx][j + ty], QA);
    }
}

__global__ void invdeg_kernel()
{
    const int r = blockIdx.x * 256 + threadIdx.x;
    float d = 0.f;
#pragma unroll
    for (int h = 0; h < 2; h++)
#pragma unroll
        for (int t = 0; t < NMAT / BN; t++) d += g_rowpart[h][t][r];
    if (d <= 1e-10f) d = 1.f;
    g_inv[r] = 2.f / d;
}

// ---------------- IMMA GEMM:  D = L @ (A^T)^T  (both K-major int8) ----------------
// MODE 0: L = g_Aq ; epilogue H = SCALE1*D + I -> g_Hq (quantized) + fp32 row partials
// MODE 1: L = g_Hq ; epilogue out = g_inv[r]*SCALE2*D (fp32)
template <int MODE>
__launch_bounds__(256, 2)
__global__ void gemm_mma(float* __restrict__ Cout)
{
    extern __shared__ char dyn_raw[];
    const uint32_t sb = smem_u32(dyn_raw);

    const int tid = threadIdx.x;
    const int lane = tid & 31;
    const int wid = tid >> 5;
    const int warp_m = wid & 3;
    const int warp_n = wid >> 2;
    const int row0 = blockIdx.y * BM;
    const int col0 = blockIdx.x * BN;

    const char* __restrict__ Lop = (MODE == 0) ? g_Aq : g_Hq;
    const char* __restrict__ Rop = g_ATq;

    // Lane-constant fragment byte offsets per k32 step (s8 frags == bf16 frag
    // geometry with 2B "elements": same ldmatrix addressing on 64B rows).
    uint32_t aoff[2][2], boff[2][4];
#pragma unroll
    for (int st = 0; st < 2; st++) {
#pragma unroll
        for (int mt = 0; mt < 2; mt++)
            aoff[st][mt] = swz(warp_m * 32 + mt * 16 + (lane & 15),
                               st * 32 + ((lane >> 4) << 4));
#pragma unroll
        for (int np = 0; np < 4; np++)
            boff[st][np] = swz(warp_n * 64 + np * 16 + (lane & 7) + ((lane >> 4) << 3),
                               st * 32 + (((lane >> 3) & 1) << 4));
    }

    auto fill = [&](int kt, int s) {
        const uint32_t ab = sb + s * STAGE_BYTES;
        const uint32_t bb = sb + SMEM_B_OFF + s * STAGE_BYTES;
#pragma unroll
        for (int i = 0; i < 2; i++) {
            const int ch = i * 256 + tid;
            const int row = ch >> 2, c16 = ch & 3;      // 4 x 16B chunks per 64B row
            CP_ASYNC16(ab + swz(row, c16 * 16),
                       Lop + (size_t)(row0 + row) * NMAT + kt * BK + c16 * 16);
            CP_ASYNC16(bb + swz(row, c16 * 16),
                       Rop + (size_t)(col0 + row) * NMAT + kt * BK + c16 * 16);
        }
    };

    auto ldsm_frag = [&](uint32_t a[2][4], uint32_t b[4][4], int s, int st) {
        const uint32_t ab = sb + s * STAGE_BYTES;
        const uint32_t bb = sb + SMEM_B_OFF + s * STAGE_BYTES;
#pragma unroll
        for (int mt = 0; mt < 2; mt++)
            LDSM_X4(a[mt][0], a[mt][1], a[mt][2], a[mt][3], ab + aoff[st][mt]);
#pragma unroll
        for (int np = 0; np < 4; np++)
            LDSM_X4(b[np][0], b[np][1], b[np][2], b[np][3], bb + boff[st][np]);
    };

    int acc[2][8][4];
#pragma unroll
    for (int mt = 0; mt < 2; mt++)
#pragma unroll
        for (int nt = 0; nt < 8; nt++)
#pragma unroll
            for (int j = 0; j < 4; j++) acc[mt][nt][j] = 0;

    auto mma_burst = [&](uint32_t a[2][4], uint32_t b[4][4]) {
#pragma unroll
        for (int mt = 0; mt < 2; mt++)
#pragma unroll
            for (int nt = 0; nt < 8; nt++) {
                uint32_t bf[2] = {b[nt >> 1][(nt & 1) * 2], b[nt >> 1][(nt & 1) * 2 + 1]};
                MMA_S8(acc[mt][nt], a[mt], bf);
            }
    };

    // Prologue
    fill(0, 0); CP_COMMIT();
    fill(1, 1); CP_COMMIT();
    fill(2, 2); CP_COMMIT();
    CP_WAIT2();
    __syncthreads();

    uint32_t a0[2][4], b0[4][4], a1[2][4], b1[4][4];
    ldsm_frag(a0, b0, 0, 0);

    for (int kt = 0; kt < KT; kt++) {
        const int s = kt & (STAGES - 1);

        ldsm_frag(a1, b1, s, 1);                 // step-1 frags of this tile
        const int f = kt + 3;
        if (f < KT) fill(f, f & (STAGES - 1));
        CP_COMMIT();

        mma_burst(a0, b0);                       // k bytes [0,32)

        if (kt + 1 < KT) {
            CP_WAIT2();
            __syncthreads();
            ldsm_frag(a0, b0, (kt + 1) & (STAGES - 1), 0);
        }

        mma_burst(a1, b1);                       // k bytes [32,64)
    }

    // ---------------- epilogue ----------------
#pragma unroll
    for (int mt = 0; mt < 2; mt++) {
        const int rA = row0 + warp_m * 32 + mt * 16 + (lane >> 2);
        const float s0 = (MODE == 0) ? SCALE1 : g_inv[rA] * SCALE2;
        const float s1 = (MODE == 0) ? SCALE1 : g_inv[rA + 8] * SCALE2;
        float rs0 = 0.f, rs1 = 0.f;
#pragma unroll
        for (int nt = 0; nt < 8; nt++) {
            const int c = col0 + warp_n * 64 + nt * 8 + (lane & 3) * 2;
            float v0 = s0 * (float)acc[mt][nt][0];
            float v1 = s0 * (float)acc[mt][nt][1];
            float v2 = s1 * (float)acc[mt][nt][2];
            float v3 = s1 * (float)acc[mt][nt][3];
            if (MODE == 0) {
                if (rA == c)         v0 += 1.0f;
                if (rA == c + 1)     v1 += 1.0f;
                if (rA + 8 == c)     v2 += 1.0f;
                if (rA + 8 == c + 1) v3 += 1.0f;
                rs0 += v0 + v1;
                rs1 += v2 + v3;
                *reinterpret_cast<char2*>(g_Hq + (size_t)rA * NMAT + c) =
                    make_char2(q8(v0, SH), q8(v1, SH));
                *reinterpret_cast<char2*>(g_Hq + (size_t)(rA + 8) * NMAT + c) =
                    make_char2(q8(v2, SH), q8(v3, SH));
            } else {
                *reinterpret_cast<float2*>(Cout + (size_t)rA * NMAT + c) = make_float2(v0, v1);
                *reinterpret_cast<float2*>(Cout + (size_t)(rA + 8) * NMAT + c) = make_float2(v2, v3);
            }
        }
        if (MODE == 0) {
            rs0 += __shfl_xor_sync(0xFFFFFFFF, rs0, 1);
            rs0 += __shfl_xor_sync(0xFFFFFFFF, rs0, 2);
            rs1 += __shfl_xor_sync(0xFFFFFFFF, rs1, 1);
            rs1 += __shfl_xor_sync(0xFFFFFFFF, rs1, 2);
            if ((lane & 3) == 0) {
                g_rowpart[warp_n][blockIdx.x][rA] = rs0;
                g_rowpart[warp_n][blockIdx.x][rA + 8] = rs1;
            }
        }
    }
}

extern "C" void kernel_launch(void* const* d_in, const int* in_sizes, int n_in,
                              void* d_out, int out_size)
{
    const float* A = (const float*)d_in[0];   // weights unused: softmax over singleton == 1
    float* out = (float*)d_out;

    cudaFuncSetAttribute(gemm_mma<0>, cudaFuncAttributeMaxDynamicSharedMemorySize, SMEM_DYN);
    cudaFuncSetAttribute(gemm_mma<1>, cudaFuncAttributeMaxDynamicSharedMemorySize, SMEM_DYN);

    convert_kernel<<<dim3(NMAT / 32, NMAT / 32), dim3(32, 8)>>>(A);
    gemm_mma<0><<<dim3(NMAT / BN, NMAT / BM), 256, SMEM_DYN>>>(out);   // H = 4*A@A + I
    invdeg_kernel<<<NMAT / 256, 256>>>();
    gemm_mma<1><<<dim3(NMAT / BN, NMAT / BM), 256, SMEM_DYN>>>(out);   // out = diag(2/deg)@(H@A)
}

// round 6
// speedup vs baseline: 2.5208x; 2.5208x over previous
#include <cuda_runtime.h>
#include <cuda_bf16.h>
#include <cstdint>

// GTN collapses (softmax over singleton axis == 1 -> gtconv == 2*A):
//   H   = 4*(A@A) + I
//   inv = 2 / rowsum(H)   (guarded)
//   out = diag(inv) @ (H @ A)
// bf16 HMMA (mma.sync m16n8k16). R5 analysis: previous 128x128 tile was
// smem-crossbar-bound (128KB/ktile vs 512 tensor cyc). This round: CTA
// 256x128, warp tile 64x32 -> 120KB smem per 1024 tensor cyc (balanced).

#define NMAT 2048
static constexpr int BM = 256;
static constexpr int BN = 128;
static constexpr int BK = 32;
static constexpr int STAGES = 4;
static constexpr int KT = NMAT / BK;             // 64
static constexpr int A_STAGE = BM * 64;          // 16KB (64B rows)
static constexpr int B_STAGE = BN * 64;          // 8KB
static constexpr int SMEM_B_OFF = STAGES * A_STAGE;            // 64KB
static constexpr int SMEM_DYN = STAGES * (A_STAGE + B_STAGE);  // 96KB

__device__ __nv_bfloat16 g_Abf[(size_t)NMAT * NMAT];
__device__ __nv_bfloat16 g_ATbf[(size_t)NMAT * NMAT];
__device__ __nv_bfloat16 g_Hbf[(size_t)NMAT * NMAT];
__device__ float g_rowpart[4][NMAT / BN][NMAT];
__device__ float g_inv[NMAT];

__device__ __forceinline__ uint32_t smem_u32(const void* p) {
    uint32_t a;
    asm("{ .reg .u64 t; cvta.to.shared.u64 t, %1; cvt.u32.u64 %0, t; }" : "=r"(a) : "l"(p));
    return a;
}
#define CP_ASYNC16(dst, src) asm volatile("cp.async.cg.shared.global [%0], [%1], 16;" :: "r"(dst), "l"(src) : "memory")
#define CP_COMMIT()          asm volatile("cp.async.commit_group;" ::: "memory")
#define CP_WAIT2()           asm volatile("cp.async.wait_group 2;" ::: "memory")
#define LDSM_X4(r0, r1, r2, r3, a) \
    asm volatile("ldmatrix.sync.aligned.m8n8.x4.shared.b16 {%0,%1,%2,%3}, [%4];" \
                 : "=r"(r0), "=r"(r1), "=r"(r2), "=r"(r3) : "r"(a))
#define MMA_BF16(c, a, b) \
    asm volatile("mma.sync.aligned.m16n8k16.row.col.f32.bf16.bf16.f32 " \
                 "{%0,%1,%2,%3}, {%4,%5,%6,%7}, {%8,%9}, {%0,%1,%2,%3};" \
                 : "+f"((c)[0]), "+f"((c)[1]), "+f"((c)[2]), "+f"((c)[3]) \
                 : "r"((a)[0]), "r"((a)[1]), "r"((a)[2]), "r"((a)[3]), "r"((b)[0]), "r"((b)[1]))

// 64B rows; XOR swizzle keeps STS/LDSM conflict-free. Additive in +16-row steps.
__device__ __forceinline__ uint32_t swz(int row, int colb) {
    return (uint32_t)(row * 64 + (colb ^ (((row >> 1) & 3) << 4)));
}

// ---------------- A -> bf16 and A^T -> bf16 ----------------
__global__ void convert_kernel(const float* __restrict__ A)
{
    __shared__ float t[32][33];
    const int tx = threadIdx.x, ty = threadIdx.y;
    const int x = blockIdx.x * 32 + tx;
    const int y0 = blockIdx.y * 32;
#pragma unroll
    for (int j = 0; j < 32; j += 8) {
        const int row = y0 + j + ty;
        const float v = A[(size_t)row * NMAT + x];
        t[j + ty][tx] = v;
        g_Abf[(size_t)row * NMAT + x] = __float2bfloat16(v);
    }
    __syncthreads();
    const int nx = y0 + tx;
#pragma unroll
    for (int j = 0; j < 32; j += 8) {
        const int orow = blockIdx.x * 32 + j + ty;
        g_ATbf[(size_t)orow * NMAT + nx] = __float2bfloat16(t[tx][j + ty]);
    }
}

__global__ void invdeg_kernel()
{
    const int r = blockIdx.x * 256 + threadIdx.x;
    float d = 0.f;
#pragma unroll
    for (int h = 0; h < 4; h++)
#pragma unroll
        for (int t = 0; t < NMAT / BN; t++) d += g_rowpart[h][t][r];
    if (d <= 1e-10f) d = 1.f;
    g_inv[r] = 2.f / d;
}

// ---------------- HMMA GEMM, CTA 256x128, warp grid 4x4, warp tile 64x32 ----------
// MODE 0: L = g_Abf ; H = 4D + I -> g_Hbf + row partials
// MODE 1: L = g_Hbf ; out = g_inv[r] * D (fp32)
template <int MODE>
__launch_bounds__(512, 1)
__global__ void gemm_mma(float* __restrict__ Cout)
{
    extern __shared__ char dyn_raw[];
    const uint32_t sb = smem_u32(dyn_raw);

    const int tid = threadIdx.x;
    const int lane = tid & 31;
    const int wid = tid >> 5;
    const int warp_m = wid & 3;        // 4 warps down M, 64 rows each
    const int warp_n = wid >> 2;       // 4 warps across N, 32 cols each
    const int row0 = blockIdx.y * BM;
    const int col0 = blockIdx.x * BN;

    const __nv_bfloat16* __restrict__ Lop = (MODE == 0) ? g_Abf : g_Hbf;
    const __nv_bfloat16* __restrict__ Rop = g_ATbf;

    // Per-step fragment base offsets (mt/np add a constant 1024 each: +16 rows
    // preserves the swizzle term since ((r+16)>>1)&3 == (r>>1)&3).
    uint32_t abase[2], bbase[2];
#pragma unroll
    for (int st = 0; st < 2; st++) {
        abase[st] = swz(warp_m * 64 + (lane & 15), st * 32 + ((lane >> 4) << 4));
        bbase[st] = swz(warp_n * 32 + (lane & 7) + ((lane >> 4) << 3),
                        st * 32 + (((lane >> 3) & 1) << 4));
    }

    // fill k-tile kt into stage s: A 1024 chunks (2/thread) + B 512 (1/thread)
    auto fill = [&](int kt, int s) {
        const uint32_t ab = sb + s * A_STAGE;
        const uint32_t bb = sb + SMEM_B_OFF + s * B_STAGE;
#pragma unroll
        for (int i = 0; i < 2; i++) {
            const int ch = i * 512 + tid;
            const int row = ch >> 2, c16 = ch & 3;
            CP_ASYNC16(ab + swz(row, c16 * 16),
                       Lop + (size_t)(row0 + row) * NMAT + kt * BK + c16 * 8);
        }
        {
            const int row = tid >> 2, c16 = tid & 3;
            CP_ASYNC16(bb + swz(row, c16 * 16),
                       Rop + (size_t)(col0 + row) * NMAT + kt * BK + c16 * 8);
        }
    };

    float acc[4][4][4];
#pragma unroll
    for (int mt = 0; mt < 4; mt++)
#pragma unroll
        for (int nt = 0; nt < 4; nt++)
#pragma unroll
            for (int j = 0; j < 4; j++) acc[mt][nt][j] = 0.f;

    // Prologue
    fill(0, 0); CP_COMMIT();
    fill(1, 1); CP_COMMIT();
    fill(2, 2); CP_COMMIT();

    for (int kt = 0; kt < KT; kt++) {
        CP_WAIT2();
        __syncthreads();
        const int s = kt & (STAGES - 1);
        const uint32_t ab = sb + s * A_STAGE;
        const uint32_t bb = sb + SMEM_B_OFF + s * B_STAGE;

        uint32_t a[4][4], b[2][4];

        // ---- step 0 ----
#pragma unroll
        for (int mt = 0; mt < 4; mt++)
            LDSM_X4(a[mt][0], a[mt][1], a[mt][2], a[mt][3], ab + abase[0] + mt * 1024);
#pragma unroll
        for (int np = 0; np < 2; np++)
            LDSM_X4(b[np][0], b[np][1], b[np][2], b[np][3], bb + bbase[0] + np * 1024);

        const int f = kt + 3;
        if (f < KT) fill(f, f & (STAGES - 1));   // overwrites stage (kt-1)&3: sync-protected
        CP_COMMIT();

#pragma unroll
        for (int mt = 0; mt < 4; mt++)
#pragma unroll
            for (int nt = 0; nt < 4; nt++) {
                uint32_t bf[2] = {b[nt >> 1][(nt & 1) * 2], b[nt >> 1][(nt & 1) * 2 + 1]};
                MMA_BF16(acc[mt][nt], a[mt], bf);
            }

        // ---- step 1 ----
#pragma unroll
        for (int mt = 0; mt < 4; mt++)
            LDSM_X4(a[mt][0], a[mt][1], a[mt][2], a[mt][3], ab + abase[1] + mt * 1024);
#pragma unroll
        for (int np = 0; np < 2; np++)
            LDSM_X4(b[np][0], b[np][1], b[np][2], b[np][3], bb + bbase[1] + np * 1024);
#pragma unroll
        for (int mt = 0; mt < 4; mt++)
#pragma unroll
            for (int nt = 0; nt < 4; nt++) {
                uint32_t bf[2] = {b[nt >> 1][(nt & 1) * 2], b[nt >> 1][(nt & 1) * 2 + 1]};
                MMA_BF16(acc[mt][nt], a[mt], bf);
            }
    }

    // ---------------- epilogue ----------------
#pragma unroll
    for (int mt = 0; mt < 4; mt++) {
        const int rA = row0 + warp_m * 64 + mt * 16 + (lane >> 2);   // rows rA, rA+8
        const float s0 = (MODE == 0) ? 4.0f : g_inv[rA];
        const float s1 = (MODE == 0) ? 4.0f : g_inv[rA + 8];
        float rs0 = 0.f, rs1 = 0.f;
#pragma unroll
        for (int nt = 0; nt < 4; nt++) {
            const int c = col0 + warp_n * 32 + nt * 8 + (lane & 3) * 2;
            float v0 = s0 * acc[mt][nt][0];
            float v1 = s0 * acc[mt][nt][1];
            float v2 = s1 * acc[mt][nt][2];
            float v3 = s1 * acc[mt][nt][3];
            if (MODE == 0) {
                if (rA == c)         v0 += 1.0f;
                if (rA == c + 1)     v1 += 1.0f;
                if (rA + 8 == c)     v2 += 1.0f;
                if (rA + 8 == c + 1) v3 += 1.0f;
                rs0 += v0 + v1;
                rs1 += v2 + v3;
                *reinterpret_cast<__nv_bfloat162*>(g_Hbf + (size_t)rA * NMAT + c) =
                    __floats2bfloat162_rn(v0, v1);
                *reinterpret_cast<__nv_bfloat162*>(g_Hbf + (size_t)(rA + 8) * NMAT + c) =
                    __floats2bfloat162_rn(v2, v3);
            } else {
                *reinterpret_cast<float2*>(Cout + (size_t)rA * NMAT + c) = make_float2(v0, v1);
                *reinterpret_cast<float2*>(Cout + (size_t)(rA + 8) * NMAT + c) = make_float2(v2, v3);
            }
        }
        if (MODE == 0) {
            rs0 += __shfl_xor_sync(0xFFFFFFFF, rs0, 1);
            rs0 += __shfl_xor_sync(0xFFFFFFFF, rs0, 2);
            rs1 += __shfl_xor_sync(0xFFFFFFFF, rs1, 1);
            rs1 += __shfl_xor_sync(0xFFFFFFFF, rs1, 2);
            if ((lane & 3) == 0) {
                g_rowpart[warp_n][blockIdx.x][rA] = rs0;
                g_rowpart[warp_n][blockIdx.x][rA + 8] = rs1;
            }
        }
    }
}

extern "C" void kernel_launch(void* const* d_in, const int* in_sizes, int n_in,
                              void* d_out, int out_size)
{
    const float* A = (const float*)d_in[0];   // weights unused: softmax over singleton == 1
    float* out = (float*)d_out;

    cudaFuncSetAttribute(gemm_mma<0>, cudaFuncAttributeMaxDynamicSharedMemorySize, SMEM_DYN);
    cudaFuncSetAttribute(gemm_mma<1>, cudaFuncAttributeMaxDynamicSharedMemorySize, SMEM_DYN);

    convert_kernel<<<dim3(NMAT / 32, NMAT / 32), dim3(32, 8)>>>(A);
    gemm_mma<0><<<dim3(NMAT / BN, NMAT / BM), 512, SMEM_DYN>>>(out);   // H = 4*A@A + I
    invdeg_kernel<<<NMAT / 256, 256>>>();
    gemm_mma<1><<<dim3(NMAT / BN, NMAT / BM), 512, SMEM_DYN>>>(out);   // out = diag(2/deg)@(H@A)
}

// round 7
// speedup vs baseline: 2.5442x; 1.0093x over previous
#include <cuda_runtime.h>
#include <cuda_bf16.h>
#include <cstdint>

// GTN collapses (softmax over singleton axis == 1 -> gtconv == 2*A):
//   H   = 4*(A@A) + I
//   inv = 2 / rowsum(H)   (guarded)
//   out = diag(inv) @ (H @ A)
// bf16 HMMA (mma.sync m16n8k16) at its sm_103 retire-rate ceiling (~53% of
// counter peak, confirmed across 3 configs). This round: fold inv-degree
// computation into GEMM2's prologue (hidden under cp.async fills), removing
// one kernel launch from the graph.

#define NMAT 2048
static constexpr int BM = 256;
static constexpr int BN = 128;
static constexpr int BK = 32;
static constexpr int STAGES = 4;
static constexpr int KT = NMAT / BK;             // 64
static constexpr int A_STAGE = BM * 64;          // 16KB (64B rows)
static constexpr int B_STAGE = BN * 64;          // 8KB
static constexpr int SMEM_B_OFF = STAGES * A_STAGE;            // 64KB
static constexpr int SMEM_DYN = STAGES * (A_STAGE + B_STAGE);  // 96KB

__device__ __nv_bfloat16 g_Abf[(size_t)NMAT * NMAT];
__device__ __nv_bfloat16 g_ATbf[(size_t)NMAT * NMAT];
__device__ __nv_bfloat16 g_Hbf[(size_t)NMAT * NMAT];
__device__ float g_rowpart[4][NMAT / BN][NMAT];

__device__ __forceinline__ uint32_t smem_u32(const void* p) {
    uint32_t a;
    asm("{ .reg .u64 t; cvta.to.shared.u64 t, %1; cvt.u32.u64 %0, t; }" : "=r"(a) : "l"(p));
    return a;
}
#define CP_ASYNC16(dst, src) asm volatile("cp.async.cg.shared.global [%0], [%1], 16;" :: "r"(dst), "l"(src) : "memory")
#define CP_COMMIT()          asm volatile("cp.async.commit_group;" ::: "memory")
#define CP_WAIT2()           asm volatile("cp.async.wait_group 2;" ::: "memory")
#define LDSM_X4(r0, r1, r2, r3, a) \
    asm volatile("ldmatrix.sync.aligned.m8n8.x4.shared.b16 {%0,%1,%2,%3}, [%4];" \
                 : "=r"(r0), "=r"(r1), "=r"(r2), "=r"(r3) : "r"(a))
#define MMA_BF16(c, a, b) \
    asm volatile("mma.sync.aligned.m16n8k16.row.col.f32.bf16.bf16.f32 " \
                 "{%0,%1,%2,%3}, {%4,%5,%6,%7}, {%8,%9}, {%0,%1,%2,%3};" \
                 : "+f"((c)[0]), "+f"((c)[1]), "+f"((c)[2]), "+f"((c)[3]) \
                 : "r"((a)[0]), "r"((a)[1]), "r"((a)[2]), "r"((a)[3]), "r"((b)[0]), "r"((b)[1]))

// 64B rows; XOR swizzle keeps STS/LDSM conflict-free. Additive in +16-row steps.
__device__ __forceinline__ uint32_t swz(int row, int colb) {
    return (uint32_t)(row * 64 + (colb ^ (((row >> 1) & 3) << 4)));
}

// ---------------- A -> bf16 and A^T -> bf16 ----------------
__global__ void convert_kernel(const float* __restrict__ A)
{
    __shared__ float t[32][33];
    const int tx = threadIdx.x, ty = threadIdx.y;
    const int x = blockIdx.x * 32 + tx;
    const int y0 = blockIdx.y * 32;
#pragma unroll
    for (int j = 0; j < 32; j += 8) {
        const int row = y0 + j + ty;
        const float v = A[(size_t)row * NMAT + x];
        t[j + ty][tx] = v;
        g_Abf[(size_t)row * NMAT + x] = __float2bfloat16(v);
    }
    __syncthreads();
    const int nx = y0 + tx;
#pragma unroll
    for (int j = 0; j < 32; j += 8) {
        const int orow = blockIdx.x * 32 + j + ty;
        g_ATbf[(size_t)orow * NMAT + nx] = __float2bfloat16(t[tx][j + ty]);
    }
}

// ---------------- HMMA GEMM, CTA 256x128, warp grid 4x4, warp tile 64x32 ----------
// MODE 0: L = g_Abf ; H = 4D + I -> g_Hbf + row partials
// MODE 1: L = g_Hbf ; out = s_inv[r] * D (fp32), inv computed in prologue
template <int MODE>
__launch_bounds__(512, 1)
__global__ void gemm_mma(float* __restrict__ Cout)
{
    extern __shared__ char dyn_raw[];
    const uint32_t sb = smem_u32(dyn_raw);
    __shared__ float s_inv[BM];

    const int tid = threadIdx.x;
    const int lane = tid & 31;
    const int wid = tid >> 5;
    const int warp_m = wid & 3;        // 4 warps down M, 64 rows each
    const int warp_n = wid >> 2;       // 4 warps across N, 32 cols each
    const int row0 = blockIdx.y * BM;
    const int col0 = blockIdx.x * BN;

    const __nv_bfloat16* __restrict__ Lop = (MODE == 0) ? g_Abf : g_Hbf;
    const __nv_bfloat16* __restrict__ Rop = g_ATbf;

    // Per-step fragment base offsets (mt/np add a constant 1024 each: +16 rows
    // preserves the swizzle term since ((r+16)>>1)&3 == (r>>1)&3).
    uint32_t abase[2], bbase[2];
#pragma unroll
    for (int st = 0; st < 2; st++) {
        abase[st] = swz(warp_m * 64 + (lane & 15), st * 32 + ((lane >> 4) << 4));
        bbase[st] = swz(warp_n * 32 + (lane & 7) + ((lane >> 4) << 3),
                        st * 32 + (((lane >> 3) & 1) << 4));
    }

    // fill k-tile kt into stage s: A 1024 chunks (2/thread) + B 512 (1/thread)
    auto fill = [&](int kt, int s) {
        const uint32_t ab = sb + s * A_STAGE;
        const uint32_t bb = sb + SMEM_B_OFF + s * B_STAGE;
#pragma unroll
        for (int i = 0; i < 2; i++) {
            const int ch = i * 512 + tid;
            const int row = ch >> 2, c16 = ch & 3;
            CP_ASYNC16(ab + swz(row, c16 * 16),
                       Lop + (size_t)(row0 + row) * NMAT + kt * BK + c16 * 8);
        }
        {
            const int row = tid >> 2, c16 = tid & 3;
            CP_ASYNC16(bb + swz(row, c16 * 16),
                       Rop + (size_t)(col0 + row) * NMAT + kt * BK + c16 * 8);
        }
    };

    float acc[4][4][4];
#pragma unroll
    for (int mt = 0; mt < 4; mt++)
#pragma unroll
        for (int nt = 0; nt < 4; nt++)
#pragma unroll
            for (int j = 0; j < 4; j++) acc[mt][nt][j] = 0.f;

    // Prologue
    fill(0, 0); CP_COMMIT();
    fill(1, 1); CP_COMMIT();
    fill(2, 2); CP_COMMIT();

    // MODE 1: compute inv-degree for this CTA's 256 rows while fills fly.
    // Reads are coalesced across r for each (h,t); fully hidden under cp.async.
    if (MODE == 1 && tid < BM) {
        const int r = row0 + tid;
        float d = 0.f;
#pragma unroll
        for (int h = 0; h < 4; h++)
#pragma unroll
            for (int t = 0; t < NMAT / BN; t++) d += g_rowpart[h][t][r];
        if (d <= 1e-10f) d = 1.f;
        s_inv[tid] = 2.f / d;
    }
    // Visibility of s_inv for the epilogue is guaranteed by the per-tile
    // __syncthreads() in the mainloop (KT >= 1).

    for (int kt = 0; kt < KT; kt++) {
        CP_WAIT2();
        __syncthreads();
        const int s = kt & (STAGES - 1);
        const uint32_t ab = sb + s * A_STAGE;
        const uint32_t bb = sb + SMEM_B_OFF + s * B_STAGE;

        uint32_t a[4][4], b[2][4];

        // ---- step 0 ----
#pragma unroll
        for (int mt = 0; mt < 4; mt++)
            LDSM_X4(a[mt][0], a[mt][1], a[mt][2], a[mt][3], ab + abase[0] + mt * 1024);
#pragma unroll
        for (int np = 0; np < 2; np++)
            LDSM_X4(b[np][0], b[np][1], b[np][2], b[np][3], bb + bbase[0] + np * 1024);

        const int f = kt + 3;
        if (f < KT) fill(f, f & (STAGES - 1));   // overwrites stage (kt-1)&3: sync-protected
        CP_COMMIT();

#pragma unroll
        for (int mt = 0; mt < 4; mt++)
#pragma unroll
            for (int nt = 0; nt < 4; nt++) {
                uint32_t bf[2] = {b[nt >> 1][(nt & 1) * 2], b[nt >> 1][(nt & 1) * 2 + 1]};
                MMA_BF16(acc[mt][nt], a[mt], bf);
            }

        // ---- step 1 ----
#pragma unroll
        for (int mt = 0; mt < 4; mt++)
            LDSM_X4(a[mt][0], a[mt][1], a[mt][2], a[mt][3], ab + abase[1] + mt * 1024);
#pragma unroll
        for (int np = 0; np < 2; np++)
            LDSM_X4(b[np][0], b[np][1], b[np][2], b[np][3], bb + bbase[1] + np * 1024);
#pragma unroll
        for (int mt = 0; mt < 4; mt++)
#pragma unroll
            for (int nt = 0; nt < 4; nt++) {
                uint32_t bf[2] = {b[nt >> 1][(nt & 1) * 2], b[nt >> 1][(nt & 1) * 2 + 1]};
                MMA_BF16(acc[mt][nt], a[mt], bf);
            }
    }

    // ---------------- epilogue ----------------
#pragma unroll
    for (int mt = 0; mt < 4; mt++) {
        const int rA = row0 + warp_m * 64 + mt * 16 + (lane >> 2);   // rows rA, rA+8
        const float s0 = (MODE == 0) ? 4.0f : s_inv[rA - row0];
        const float s1 = (MODE == 0) ? 4.0f : s_inv[rA + 8 - row0];
        float rs0 = 0.f, rs1 = 0.f;
#pragma unroll
        for (int nt = 0; nt < 4; nt++) {
            const int c = col0 + warp_n * 32 + nt * 8 + (lane & 3) * 2;
            float v0 = s0 * acc[mt][nt][0];
            float v1 = s0 * acc[mt][nt][1];
            float v2 = s1 * acc[mt][nt][2];
            float v3 = s1 * acc[mt][nt][3];
            if (MODE == 0) {
                if (rA == c)         v0 += 1.0f;
                if (rA == c + 1)     v1 += 1.0f;
                if (rA + 8 == c)     v2 += 1.0f;
                if (rA + 8 == c + 1) v3 += 1.0f;
                rs0 += v0 + v1;
                rs1 += v2 + v3;
                *reinterpret_cast<__nv_bfloat162*>(g_Hbf + (size_t)rA * NMAT + c) =
                    __floats2bfloat162_rn(v0, v1);
                *reinterpret_cast<__nv_bfloat162*>(g_Hbf + (size_t)(rA + 8) * NMAT + c) =
                    __floats2bfloat162_rn(v2, v3);
            } else {
                *reinterpret_cast<float2*>(Cout + (size_t)rA * NMAT + c) = make_float2(v0, v1);
                *reinterpret_cast<float2*>(Cout + (size_t)(rA + 8) * NMAT + c) = make_float2(v2, v3);
            }
        }
        if (MODE == 0) {
            rs0 += __shfl_xor_sync(0xFFFFFFFF, rs0, 1);
            rs0 += __shfl_xor_sync(0xFFFFFFFF, rs0, 2);
            rs1 += __shfl_xor_sync(0xFFFFFFFF, rs1, 1);
            rs1 += __shfl_xor_sync(0xFFFFFFFF, rs1, 2);
            if ((lane & 3) == 0) {
                g_rowpart[warp_n][blockIdx.x][rA] = rs0;
                g_rowpart[warp_n][blockIdx.x][rA + 8] = rs1;
            }
        }
    }
}

extern "C" void kernel_launch(void* const* d_in, const int* in_sizes, int n_in,
                              void* d_out, int out_size)
{
    const float* A = (const float*)d_in[0];   // weights unused: softmax over singleton == 1
    float* out = (float*)d_out;

    cudaFuncSetAttribute(gemm_mma<0>, cudaFuncAttributeMaxDynamicSharedMemorySize, SMEM_DYN);
    cudaFuncSetAttribute(gemm_mma<1>, cudaFuncAttributeMaxDynamicSharedMemorySize, SMEM_DYN);

    convert_kernel<<<dim3(NMAT / 32, NMAT / 32), dim3(32, 8)>>>(A);
    gemm_mma<0><<<dim3(NMAT / BN, NMAT / BM), 512, SMEM_DYN>>>(out);   // H = 4*A@A + I
    gemm_mma<1><<<dim3(NMAT / BN, NMAT / BM), 512, SMEM_DYN>>>(out);   // out = diag(2/deg)@(H@A)
}

// round 9
// speedup vs baseline: 2.5681x; 1.0094x over previous
#include <cuda_runtime.h>
#include <cuda_bf16.h>
#include <cstdint>
#include <cstring>

// GTN collapses (softmax over singleton axis == 1 -> gtconv == 2*A):
//   H   = 4*(A@A) + I
//   inv = 2 / rowsum(H)   (guarded)
//   out = diag(inv) @ (H @ A)
// bf16 HMMA (mma.sync m16n8k16) at its sm_103 retire-rate ceiling (~53%,
// confirmed across 3 configs -> GEMMs untouched). This round: vectorized
// 64x64-tile converter (float4 loads, 8B bf16x4 stores) to cut its 9.3us.

#define NMAT 2048
static constexpr int BM = 256;
static constexpr int BN = 128;
static constexpr int BK = 32;
static constexpr int STAGES = 4;
static constexpr int KT = NMAT / BK;             // 64
static constexpr int A_STAGE = BM * 64;          // 16KB (64B rows)
static constexpr int B_STAGE = BN * 64;          // 8KB
static constexpr int SMEM_B_OFF = STAGES * A_STAGE;            // 64KB
static constexpr int SMEM_DYN = STAGES * (A_STAGE + B_STAGE);  // 96KB

__device__ __nv_bfloat16 g_Abf[(size_t)NMAT * NMAT];
__device__ __nv_bfloat16 g_ATbf[(size_t)NMAT * NMAT];
__device__ __nv_bfloat16 g_Hbf[(size_t)NMAT * NMAT];
__device__ float g_rowpart[4][NMAT / BN][NMAT];

__device__ __forceinline__ uint32_t smem_u32(const void* p) {
    uint32_t a;
    asm("{ .reg .u64 t; cvta.to.shared.u64 t, %1; cvt.u32.u64 %0, t; }" : "=r"(a) : "l"(p));
    return a;
}
#define CP_ASYNC16(dst, src) asm volatile("cp.async.cg.shared.global [%0], [%1], 16;" :: "r"(dst), "l"(src) : "memory")
#define CP_COMMIT()          asm volatile("cp.async.commit_group;" ::: "memory")
#define CP_WAIT2()           asm volatile("cp.async.wait_group 2;" ::: "memory")
#define LDSM_X4(r0, r1, r2, r3, a) \
    asm volatile("ldmatrix.sync.aligned.m8n8.x4.shared.b16 {%0,%1,%2,%3}, [%4];" \
                 : "=r"(r0), "=r"(r1), "=r"(r2), "=r"(r3) : "r"(a))
#define MMA_BF16(c, a, b) \
    asm volatile("mma.sync.aligned.m16n8k16.row.col.f32.bf16.bf16.f32 " \
                 "{%0,%1,%2,%3}, {%4,%5,%6,%7}, {%8,%9}, {%0,%1,%2,%3};" \
                 : "+f"((c)[0]), "+f"((c)[1]), "+f"((c)[2]), "+f"((c)[3]) \
                 : "r"((a)[0]), "r"((a)[1]), "r"((a)[2]), "r"((a)[3]), "r"((b)[0]), "r"((b)[1]))

__device__ __forceinline__ uint32_t swz(int row, int colb) {
    return (uint32_t)(row * 64 + (colb ^ (((row >> 1) & 3) << 4)));
}

__device__ __forceinline__ uint32_t bf2_bits(__nv_bfloat162 v) {
    uint32_t u;
    memcpy(&u, &v, 4);
    return u;
}
__device__ __forceinline__ uint2 pack4_bf16(float a, float b, float c, float d) {
    uint2 r;
    r.x = bf2_bits(__floats2bfloat162_rn(a, b));
    r.y = bf2_bits(__floats2bfloat162_rn(c, d));
    return r;
}

// ---------------- A -> bf16 and A^T -> bf16 (64x64 tiles, vectorized) ----------------
__global__ void convert_kernel(const float* __restrict__ A)
{
    __shared__ float t[64][65];
    const int tid = threadIdx.x;
    const int c4 = tid & 15;          // 16 threads x 4 cols = 64
    const int rg = tid >> 4;          // 0..15
    const int x0 = blockIdx.x * 64 + c4 * 4;
    const int y0 = blockIdx.y * 64;

#pragma unroll
    for (int p = 0; p < 4; p++) {
        const int rl = p * 16 + rg;
        const int row = y0 + rl;
        const float4 v = *reinterpret_cast<const float4*>(A + (size_t)row * NMAT + x0);
        t[rl][c4 * 4 + 0] = v.x;
        t[rl][c4 * 4 + 1] = v.y;
        t[rl][c4 * 4 + 2] = v.z;
        t[rl][c4 * 4 + 3] = v.w;
        *reinterpret_cast<uint2*>(g_Abf + (size_t)row * NMAT + x0) =
            pack4_bf16(v.x, v.y, v.z, v.w);
    }
    __syncthreads();

    // Transposed: output row o = bx*64 + rl, contiguous cols = y0 + c4*4 ..
#pragma unroll
    for (int p = 0; p < 4; p++) {
        const int rl = p * 16 + rg;
        const int orow = blockIdx.x * 64 + rl;
        const float v0 = t[c4 * 4 + 0][rl];
        const float v1 = t[c4 * 4 + 1][rl];
        const float v2 = t[c4 * 4 + 2][rl];
        const float v3 = t[c4 * 4 + 3][rl];
        *reinterpret_cast<uint2*>(g_ATbf + (size_t)orow * NMAT + y0 + c4 * 4) =
            pack4_bf16(v0, v1, v2, v3);
    }
}

// ---------------- HMMA GEMM, CTA 256x128, warp grid 4x4, warp tile 64x32 ----------
// MODE 0: L = g_Abf ; H = 4D + I -> g_Hbf + row partials
// MODE 1: L = g_Hbf ; out = s_inv[r] * D (fp32), inv computed in prologue
template <int MODE>
__launch_bounds__(512, 1)
__global__ void gemm_mma(float* __restrict__ Cout)
{
    extern __shared__ char dyn_raw[];
    const uint32_t sb = smem_u32(dyn_raw);
    __shared__ float s_inv[BM];

    const int tid = threadIdx.x;
    const int lane = tid & 31;
    const int wid = tid >> 5;
    const int warp_m = wid & 3;
    const int warp_n = wid >> 2;
    const int row0 = blockIdx.y * BM;
    const int col0 = blockIdx.x * BN;

    const __nv_bfloat16* __restrict__ Lop = (MODE == 0) ? g_Abf : g_Hbf;
    const __nv_bfloat16* __restrict__ Rop = g_ATbf;

    uint32_t abase[2], bbase[2];
#pragma unroll
    for (int st = 0; st < 2; st++) {
        abase[st] = swz(warp_m * 64 + (lane & 15), st * 32 + ((lane >> 4) << 4));
        bbase[st] = swz(warp_n * 32 + (lane & 7) + ((lane >> 4) << 3),
                        st * 32 + (((lane >> 3) & 1) << 4));
    }

    auto fill = [&](int kt, int s) {
        const uint32_t ab = sb + s * A_STAGE;
        const uint32_t bb = sb + SMEM_B_OFF + s * B_STAGE;
#pragma unroll
        for (int i = 0; i < 2; i++) {
            const int ch = i * 512 + tid;
            const int row = ch >> 2, c16 = ch & 3;
            CP_ASYNC16(ab + swz(row, c16 * 16),
                       Lop + (size_t)(row0 + row) * NMAT + kt * BK + c16 * 8);
        }
        {
            const int row = tid >> 2, c16 = tid & 3;
            CP_ASYNC16(bb + swz(row, c16 * 16),
                       Rop + (size_t)(col0 + row) * NMAT + kt * BK + c16 * 8);
        }
    };

    float acc[4][4][4];
#pragma unroll
    for (int mt = 0; mt < 4; mt++)
#pragma unroll
        for (int nt = 0; nt < 4; nt++)
#pragma unroll
            for (int j = 0; j < 4; j++) acc[mt][nt][j] = 0.f;

    fill(0, 0); CP_COMMIT();
    fill(1, 1); CP_COMMIT();
    fill(2, 2); CP_COMMIT();

    // MODE 1: inv-degree for this CTA's rows, hidden under the prologue fills.
    if (MODE == 1 && tid < BM) {
        const int r = row0 + tid;
        float d = 0.f;
#pragma unroll
        for (int h = 0; h < 4; h++)
#pragma unroll
            for (int t = 0; t < NMAT / BN; t++) d += g_rowpart[h][t][r];
        if (d <= 1e-10f) d = 1.f;
        s_inv[tid] = 2.f / d;
    }
    // s_inv visibility: the mainloop's __syncthreads() (KT >= 1) orders it.

    for (int kt = 0; kt < KT; kt++) {
        CP_WAIT2();
        __syncthreads();
        const int s = kt & (STAGES - 1);
        const uint32_t ab = sb + s * A_STAGE;
        const uint32_t bb = sb + SMEM_B_OFF + s * B_STAGE;

        uint32_t a[4][4], b[2][4];

        // ---- step 0 ----
#pragma unroll
        for (int mt = 0; mt < 4; mt++)
            LDSM_X4(a[mt][0], a[mt][1], a[mt][2], a[mt][3], ab + abase[0] + mt * 1024);
#pragma unroll
        for (int np = 0; np < 2; np++)
            LDSM_X4(b[np][0], b[np][1], b[np][2], b[np][3], bb + bbase[0] + np * 1024);

        const int f = kt + 3;
        if (f < KT) fill(f, f & (STAGES - 1));
        CP_COMMIT();

#pragma unroll
        for (int mt = 0; mt < 4; mt++)
#pragma unroll
            for (int nt = 0; nt < 4; nt++) {
                uint32_t bf[2] = {b[nt >> 1][(nt & 1) * 2], b[nt >> 1][(nt & 1) * 2 + 1]};
                MMA_BF16(acc[mt][nt], a[mt], bf);
            }

        // ---- step 1 ----
#pragma unroll
        for (int mt = 0; mt < 4; mt++)
            LDSM_X4(a[mt][0], a[mt][1], a[mt][2], a[mt][3], ab + abase[1] + mt * 1024);
#pragma unroll
        for (int np = 0; np < 2; np++)
            LDSM_X4(b[np][0], b[np][1], b[np][2], b[np][3], bb + bbase[1] + np * 1024);
#pragma unroll
        for (int mt = 0; mt < 4; mt++)
#pragma unroll
            for (int nt = 0; nt < 4; nt++) {
                uint32_t bf[2] = {b[nt >> 1][(nt & 1) * 2], b[nt >> 1][(nt & 1) * 2 + 1]};
                MMA_BF16(acc[mt][nt], a[mt], bf);
            }
    }

    // ---------------- epilogue ----------------
#pragma unroll
    for (int mt = 0; mt < 4; mt++) {
        const int rA = row0 + warp_m * 64 + mt * 16 + (lane >> 2);
        const float s0 = (MODE == 0) ? 4.0f : s_inv[rA - row0];
        const float s1 = (MODE == 0) ? 4.0f : s_inv[rA + 8 - row0];
        float rs0 = 0.f, rs1 = 0.f;
#pragma unroll
        for (int nt = 0; nt < 4; nt++) {
            const int c = col0 + warp_n * 32 + nt * 8 + (lane & 3) * 2;
            float v0 = s0 * acc[mt][nt][0];
            float v1 = s0 * acc[mt][nt][1];
            float v2 = s1 * acc[mt][nt][2];
            float v3 = s1 * acc[mt][nt][3];
            if (MODE == 0) {
                if (rA == c)         v0 += 1.0f;
                if (rA == c + 1)     v1 += 1.0f;
                if (rA + 8 == c)     v2 += 1.0f;
                if (rA + 8 == c + 1) v3 += 1.0f;
                rs0 += v0 + v1;
                rs1 += v2 + v3;
                *reinterpret_cast<__nv_bfloat162*>(g_Hbf + (size_t)rA * NMAT + c) =
                    __floats2bfloat162_rn(v0, v1);
                *reinterpret_cast<__nv_bfloat162*>(g_Hbf + (size_t)(rA + 8) * NMAT + c) =
                    __floats2bfloat162_rn(v2, v3);
            } else {
                *reinterpret_cast<float2*>(Cout + (size_t)rA * NMAT + c) = make_float2(v0, v1);
                *reinterpret_cast<float2*>(Cout + (size_t)(rA + 8) * NMAT + c) = make_float2(v2, v3);
            }
        }
        if (MODE == 0) {
            rs0 += __shfl_xor_sync(0xFFFFFFFF, rs0, 1);
            rs0 += __shfl_xor_sync(0xFFFFFFFF, rs0, 2);
            rs1 += __shfl_xor_sync(0xFFFFFFFF, rs1, 1);
            rs1 += __shfl_xor_sync(0xFFFFFFFF, rs1, 2);
            if ((lane & 3) == 0) {
                g_rowpart[warp_n][blockIdx.x][rA] = rs0;
                g_rowpart[warp_n][blockIdx.x][rA + 8] = rs1;
            }
        }
    }
}

extern "C" void kernel_launch(void* const* d_in, const int* in_sizes, int n_in,
                              void* d_out, int out_size)
{
    const float* A = (const float*)d_in[0];   // weights unused: softmax over singleton == 1
    float* out = (float*)d_out;

    cudaFuncSetAttribute(gemm_mma<0>, cudaFuncAttributeMaxDynamicSharedMemorySize, SMEM_DYN);
    cudaFuncSetAttribute(gemm_mma<1>, cudaFuncAttributeMaxDynamicSharedMemorySize, SMEM_DYN);

    convert_kernel<<<dim3(NMAT / 64, NMAT / 64), 256>>>(A);
    gemm_mma<0><<<dim3(NMAT / BN, NMAT / BM), 512, SMEM_DYN>>>(out);   // H = 4*A@A + I
    gemm_mma<1><<<dim3(NMAT / BN, NMAT / BM), 512, SMEM_DYN>>>(out);   // out = diag(2/deg)@(H@A)
}

// round 10
// speedup vs baseline: 2.5741x; 1.0023x over previous
#include <cuda_runtime.h>
#include <cuda_bf16.h>
#include <cstdint>
#include <cstring>

// GTN collapses (softmax over singleton axis == 1 -> gtconv == 2*A):
//   H   = 4*(A@A) + I
//   inv = 2 / rowsum(H)   (guarded)
//   out = diag(inv) @ (H @ A)
// bf16 HMMA at its sm_103 retire ceiling (~53%, GEMM mainloop protected).
// This round: B operand loaded with ldmatrix.trans from row-major A k-rows,
// eliminating the A^T copy; converter becomes pure streaming quantize.

#define NMAT 2048
static constexpr int BM = 256;
static constexpr int BN = 128;
static constexpr int BK = 32;
static constexpr int STAGES = 4;
static constexpr int KT = NMAT / BK;             // 64
static constexpr int A_STAGE = BM * 64;          // 16KB (64B rows, M-major)
static constexpr int B_STAGE = BK * 256;         // 8KB  (256B rows, K-major)
static constexpr int SMEM_B_OFF = STAGES * A_STAGE;            // 64KB
static constexpr int SMEM_DYN = STAGES * (A_STAGE + B_STAGE);  // 96KB

__device__ __nv_bfloat16 g_Abf[(size_t)NMAT * NMAT];
__device__ __nv_bfloat16 g_Hbf[(size_t)NMAT * NMAT];
__device__ float g_rowpart[4][NMAT / BN][NMAT];

__device__ __forceinline__ uint32_t smem_u32(const void* p) {
    uint32_t a;
    asm("{ .reg .u64 t; cvta.to.shared.u64 t, %1; cvt.u32.u64 %0, t; }" : "=r"(a) : "l"(p));
    return a;
}
#define CP_ASYNC16(dst, src) asm volatile("cp.async.cg.shared.global [%0], [%1], 16;" :: "r"(dst), "l"(src) : "memory")
#define CP_COMMIT()          asm volatile("cp.async.commit_group;" ::: "memory")
#define CP_WAIT2()           asm volatile("cp.async.wait_group 2;" ::: "memory")
#define LDSM_X4(r0, r1, r2, r3, a) \
    asm volatile("ldmatrix.sync.aligned.m8n8.x4.shared.b16 {%0,%1,%2,%3}, [%4];" \
                 : "=r"(r0), "=r"(r1), "=r"(r2), "=r"(r3) : "r"(a))
#define LDSM_X4T(r0, r1, r2, r3, a) \
    asm volatile("ldmatrix.sync.aligned.m8n8.x4.trans.shared.b16 {%0,%1,%2,%3}, [%4];" \
                 : "=r"(r0), "=r"(r1), "=r"(r2), "=r"(r3) : "r"(a))
#define MMA_BF16(c, a, b) \
    asm volatile("mma.sync.aligned.m16n8k16.row.col.f32.bf16.bf16.f32 " \
                 "{%0,%1,%2,%3}, {%4,%5,%6,%7}, {%8,%9}, {%0,%1,%2,%3};" \
                 : "+f"((c)[0]), "+f"((c)[1]), "+f"((c)[2]), "+f"((c)[3]) \
                 : "r"((a)[0]), "r"((a)[1]), "r"((a)[2]), "r"((a)[3]), "r"((b)[0]), "r"((b)[1]))

// A stage: 64B rows (M-major), XOR swizzle
__device__ __forceinline__ uint32_t swzA(int row, int colb) {
    return (uint32_t)(row * 64 + (colb ^ (((row >> 1) & 3) << 4)));
}
// B stage: 256B k-rows; 16B chunk c at row k lives at chunk c ^ (k&7).
__device__ __forceinline__ uint32_t swzB(int k, int chunk) {
    return (uint32_t)(k * 256 + ((chunk ^ (k & 7)) << 4));
}

__device__ __forceinline__ uint32_t bf2_bits(__nv_bfloat162 v) {
    uint32_t u;
    memcpy(&u, &v, 4);
    return u;
}

// ---------------- A -> bf16 (pure streaming, no transpose) ----------------
__global__ void convert_kernel(const float* __restrict__ A)
{
    const size_t base = (size_t)blockIdx.x * 4096 + (size_t)threadIdx.x * 16;
    float4 v[4];
#pragma unroll
    for (int i = 0; i < 4; i++)
        v[i] = *reinterpret_cast<const float4*>(A + base + i * 4);
    uint4 o0, o1;
    o0.x = bf2_bits(__floats2bfloat162_rn(v[0].x, v[0].y));
    o0.y = bf2_bits(__floats2bfloat162_rn(v[0].z, v[0].w));
    o0.z = bf2_bits(__floats2bfloat162_rn(v[1].x, v[1].y));
    o0.w = bf2_bits(__floats2bfloat162_rn(v[1].z, v[1].w));
    o1.x = bf2_bits(__floats2bfloat162_rn(v[2].x, v[2].y));
    o1.y = bf2_bits(__floats2bfloat162_rn(v[2].z, v[2].w));
    o1.z = bf2_bits(__floats2bfloat162_rn(v[3].x, v[3].y));
    o1.w = bf2_bits(__floats2bfloat162_rn(v[3].z, v[3].w));
    *reinterpret_cast<uint4*>(g_Abf + base) = o0;
    *reinterpret_cast<uint4*>(g_Abf + base + 8) = o1;
}

// ---------------- HMMA GEMM, CTA 256x128, warp grid 4x4, warp tile 64x32 ----------
// D = L @ B where B[k][n] = A[k][n] loaded via ldmatrix.trans (col-fragments).
// MODE 0: L = g_Abf ; H = 4D + I -> g_Hbf + row partials
// MODE 1: L = g_Hbf ; out = s_inv[r] * D (fp32), inv computed in prologue
template <int MODE>
__launch_bounds__(512, 1)
__global__ void gemm_mma(float* __restrict__ Cout)
{
    extern __shared__ char dyn_raw[];
    const uint32_t sb = smem_u32(dyn_raw);
    __shared__ float s_inv[BM];

    const int tid = threadIdx.x;
    const int lane = tid & 31;
    const int wid = tid >> 5;
    const int warp_m = wid & 3;
    const int warp_n = wid >> 2;
    const int row0 = blockIdx.y * BM;
    const int col0 = blockIdx.x * BN;

    const __nv_bfloat16* __restrict__ Lop = (MODE == 0) ? g_Abf : g_Hbf;
    const __nv_bfloat16* __restrict__ Rop = g_Abf;   // B = A k-rows, both modes

    // A fragments: non-trans, lane-constant offsets per k16 step
    uint32_t abase[2];
#pragma unroll
    for (int st = 0; st < 2; st++)
        abase[st] = swzA(warp_m * 64 + (lane & 15), st * 32 + ((lane >> 4) << 4));

    // B fragments: ldmatrix.x4.trans. Matrix m = lane>>3 maps to
    // (k-block = m&1, n-block = m>>1); lane row r = lane&7.
    // Address = k-row (st*16 + (m&1)*8 + r), 16B chunk (warp_n*4 + np*2 + (m>>1)).
    uint32_t bbase[2][2];
    {
        const int m = lane >> 3, r = lane & 7;
#pragma unroll
        for (int st = 0; st < 2; st++)
#pragma unroll
            for (int np = 0; np < 2; np++)
                bbase[st][np] = swzB(st * 16 + ((m & 1) << 3) + r,
                                     warp_n * 4 + np * 2 + (m >> 1));
    }

    // fill k-tile kt into stage s: A 1024 chunks (2/thread) + B 512 (1/thread)
    auto fill = [&](int kt, int s) {
        const uint32_t ab = sb + s * A_STAGE;
        const uint32_t bb = sb + SMEM_B_OFF + s * B_STAGE;
#pragma unroll
        for (int i = 0; i < 2; i++) {
            const int ch = i * 512 + tid;
            const int row = ch >> 2, c16 = ch & 3;
            CP_ASYNC16(ab + swzA(row, c16 * 16),
                       Lop + (size_t)(row0 + row) * NMAT + kt * BK + c16 * 8);
        }
        {
            const int krow = tid >> 4, c = tid & 15;    // 32 k-rows x 16 chunks
            CP_ASYNC16(bb + swzB(krow, c),
                       Rop + (size_t)(kt * BK + krow) * NMAT + col0 + c * 8);
        }
    };

    float acc[4][4][4];
#pragma unroll
    for (int mt = 0; mt < 4; mt++)
#pragma unroll
        for (int nt = 0; nt < 4; nt++)
#pragma unroll
            for (int j = 0; j < 4; j++) acc[mt][nt][j] = 0.f;

    fill(0, 0); CP_COMMIT();
    fill(1, 1); CP_COMMIT();
    fill(2, 2); CP_COMMIT();

    // MODE 1: inv-degree for this CTA's rows, hidden under the prologue fills.
    if (MODE == 1 && tid < BM) {
        const int r = row0 + tid;
        float d = 0.f;
#pragma unroll
        for (int h = 0; h < 4; h++)
#pragma unroll
            for (int t = 0; t < NMAT / BN; t++) d += g_rowpart[h][t][r];
        if (d <= 1e-10f) d = 1.f;
        s_inv[tid] = 2.f / d;
    }
    // s_inv visibility: the mainloop's __syncthreads() (KT >= 1) orders it.

    for (int kt = 0; kt < KT; kt++) {
        CP_WAIT2();
        __syncthreads();
        const int s = kt & (STAGES - 1);
        const uint32_t ab = sb + s * A_STAGE;
        const uint32_t bb = sb + SMEM_B_OFF + s * B_STAGE;

        uint32_t a[4][4], b[2][4];

        // ---- step 0 ----
#pragma unroll
        for (int mt = 0; mt < 4; mt++)
            LDSM_X4(a[mt][0], a[mt][1], a[mt][2], a[mt][3], ab + abase[0] + mt * 1024);
#pragma unroll
        for (int np = 0; np < 2; np++)
            LDSM_X4T(b[np][0], b[np][1], b[np][2], b[np][3], bb + bbase[0][np]);

        const int f = kt + 3;
        if (f < KT) fill(f, f & (STAGES - 1));
        CP_COMMIT();

#pragma unroll
        for (int mt = 0; mt < 4; mt++)
#pragma unroll
            for (int nt = 0; nt < 4; nt++) {
                uint32_t bf[2] = {b[nt >> 1][(nt & 1) * 2], b[nt >> 1][(nt & 1) * 2 + 1]};
                MMA_BF16(acc[mt][nt], a[mt], bf);
            }

        // ---- step 1 ----
#pragma unroll
        for (int mt = 0; mt < 4; mt++)
            LDSM_X4(a[mt][0], a[mt][1], a[mt][2], a[mt][3], ab + abase[1] + mt * 1024);
#pragma unroll
        for (int np = 0; np < 2; np++)
            LDSM_X4T(b[np][0], b[np][1], b[np][2], b[np][3], bb + bbase[1][np]);
#pragma unroll
        for (int mt = 0; mt < 4; mt++)
#pragma unroll
            for (int nt = 0; nt < 4; nt++) {
                uint32_t bf[2] = {b[nt >> 1][(nt & 1) * 2], b[nt >> 1][(nt & 1) * 2 + 1]};
                MMA_BF16(acc[mt][nt], a[mt], bf);
            }
    }

    // ---------------- epilogue ----------------
#pragma unroll
    for (int mt = 0; mt < 4; mt++) {
        const int rA = row0 + warp_m * 64 + mt * 16 + (lane >> 2);
        const float s0 = (MODE == 0) ? 4.0f : s_inv[rA - row0];
        const float s1 = (MODE == 0) ? 4.0f : s_inv[rA + 8 - row0];
        float rs0 = 0.f, rs1 = 0.f;
#pragma unroll
        for (int nt = 0; nt < 4; nt++) {
            const int c = col0 + warp_n * 32 + nt * 8 + (lane & 3) * 2;
            float v0 = s0 * acc[mt][nt][0];
            float v1 = s0 * acc[mt][nt][1];
            float v2 = s1 * acc[mt][nt][2];
            float v3 = s1 * acc[mt][nt][3];
            if (MODE == 0) {
                if (rA == c)         v0 += 1.0f;
                if (rA == c + 1)     v1 += 1.0f;
                if (rA + 8 == c)     v2 += 1.0f;
                if (rA + 8 == c + 1) v3 += 1.0f;
                rs0 += v0 + v1;
                rs1 += v2 + v3;
                *reinterpret_cast<__nv_bfloat162*>(g_Hbf + (size_t)rA * NMAT + c) =
                    __floats2bfloat162_rn(v0, v1);
                *reinterpret_cast<__nv_bfloat162*>(g_Hbf + (size_t)(rA + 8) * NMAT + c) =
                    __floats2bfloat162_rn(v2, v3);
            } else {
                *reinterpret_cast<float2*>(Cout + (size_t)rA * NMAT + c) = make_float2(v0, v1);
                *reinterpret_cast<float2*>(Cout + (size_t)(rA + 8) * NMAT + c) = make_float2(v2, v3);
            }
        }
        if (MODE == 0) {
            rs0 += __shfl_xor_sync(0xFFFFFFFF, rs0, 1);
            rs0 += __shfl_xor_sync(0xFFFFFFFF, rs0, 2);
            rs1 += __shfl_xor_sync(0xFFFFFFFF, rs1, 1);
            rs1 += __shfl_xor_sync(0xFFFFFFFF, rs1, 2);
            if ((lane & 3) == 0) {
                g_rowpart[warp_n][blockIdx.x][rA] = rs0;
                g_rowpart[warp_n][blockIdx.x][rA + 8] = rs1;
            }
        }
    }
}

extern "C" void kernel_launch(void* const* d_in, const int* in_sizes, int n_in,
                              void* d_out, int out_size)
{
    const float* A = (const float*)d_in[0];   // weights unused: softmax over singleton == 1
    float* out = (float*)d_out;

    cudaFuncSetAttribute(gemm_mma<0>, cudaFuncAttributeMaxDynamicSharedMemorySize, SMEM_DYN);
    cudaFuncSetAttribute(gemm_mma<1>, cudaFuncAttributeMaxDynamicSharedMemorySize, SMEM_DYN);

    convert_kernel<<<NMAT * NMAT / 4096, 256>>>(A);
    gemm_mma<0><<<dim3(NMAT / BN, NMAT / BM), 512, SMEM_DYN>>>(out);   // H = 4*A@A + I
    gemm_mma<1><<<dim3(NMAT / BN, NMAT / BM), 512, SMEM_DYN>>>(out);   // out = diag(2/deg)@(H@A)
}

// round 11
// speedup vs baseline: 2.6234x; 1.0191x over previous
#include <cuda_runtime.h>
#include <cuda_bf16.h>
#include <cstdint>
#include <cstring>

// GTN collapses (softmax over singleton axis == 1 -> gtconv == 2*A):
//   H   = 4*(A@A) + I
//   inv = 2 / rowsum(H)   (guarded)
//   out = diag(inv) @ (H @ A)
// bf16 HMMA at its sm_103 retire ceiling (~53%, GEMM mainloop protected).
// B operand loaded with ldmatrix.trans from row-major A k-rows (no A^T copy).
// This round: fully-coalesced streaming converter (was 64B-strided -> 16
// L1 wavefronts per LDG; now 1).

#define NMAT 2048
static constexpr int BM = 256;
static constexpr int BN = 128;
static constexpr int BK = 32;
static constexpr int STAGES = 4;
static constexpr int KT = NMAT / BK;             // 64
static constexpr int A_STAGE = BM * 64;          // 16KB (64B rows, M-major)
static constexpr int B_STAGE = BK * 256;         // 8KB  (256B rows, K-major)
static constexpr int SMEM_B_OFF = STAGES * A_STAGE;            // 64KB
static constexpr int SMEM_DYN = STAGES * (A_STAGE + B_STAGE);  // 96KB

__device__ __nv_bfloat16 g_Abf[(size_t)NMAT * NMAT];
__device__ __nv_bfloat16 g_Hbf[(size_t)NMAT * NMAT];
__device__ float g_rowpart[4][NMAT / BN][NMAT];

__device__ __forceinline__ uint32_t smem_u32(const void* p) {
    uint32_t a;
    asm("{ .reg .u64 t; cvta.to.shared.u64 t, %1; cvt.u32.u64 %0, t; }" : "=r"(a) : "l"(p));
    return a;
}
#define CP_ASYNC16(dst, src) asm volatile("cp.async.cg.shared.global [%0], [%1], 16;" :: "r"(dst), "l"(src) : "memory")
#define CP_COMMIT()          asm volatile("cp.async.commit_group;" ::: "memory")
#define CP_WAIT2()           asm volatile("cp.async.wait_group 2;" ::: "memory")
#define LDSM_X4(r0, r1, r2, r3, a) \
    asm volatile("ldmatrix.sync.aligned.m8n8.x4.shared.b16 {%0,%1,%2,%3}, [%4];" \
                 : "=r"(r0), "=r"(r1), "=r"(r2), "=r"(r3) : "r"(a))
#define LDSM_X4T(r0, r1, r2, r3, a) \
    asm volatile("ldmatrix.sync.aligned.m8n8.x4.trans.shared.b16 {%0,%1,%2,%3}, [%4];" \
                 : "=r"(r0), "=r"(r1), "=r"(r2), "=r"(r3) : "r"(a))
#define MMA_BF16(c, a, b) \
    asm volatile("mma.sync.aligned.m16n8k16.row.col.f32.bf16.bf16.f32 " \
                 "{%0,%1,%2,%3}, {%4,%5,%6,%7}, {%8,%9}, {%0,%1,%2,%3};" \
                 : "+f"((c)[0]), "+f"((c)[1]), "+f"((c)[2]), "+f"((c)[3]) \
                 : "r"((a)[0]), "r"((a)[1]), "r"((a)[2]), "r"((a)[3]), "r"((b)[0]), "r"((b)[1]))

// A stage: 64B rows (M-major), XOR swizzle
__device__ __forceinline__ uint32_t swzA(int row, int colb) {
    return (uint32_t)(row * 64 + (colb ^ (((row >> 1) & 3) << 4)));
}
// B stage: 256B k-rows; 16B chunk c at row k lives at chunk c ^ (k&7).
__device__ __forceinline__ uint32_t swzB(int k, int chunk) {
    return (uint32_t)(k * 256 + ((chunk ^ (k & 7)) << 4));
}

__device__ __forceinline__ uint32_t bf2_bits(__nv_bfloat162 v) {
    uint32_t u;
    memcpy(&u, &v, 4);
    return u;
}

// ---------------- A -> bf16 (streaming, fully coalesced) ----------------
// Thread t, iter i handles float4 index blk*1024 + i*256 + t: consecutive
// lanes -> consecutive 16B chunks (1 wavefront/request); uint2 stores are
// 256B contiguous per warp. 4 independent loads + 4 independent stores.
__global__ void convert_kernel(const float* __restrict__ A)
{
    const float4* __restrict__ A4 = reinterpret_cast<const float4*>(A);
    uint2* __restrict__ O2 = reinterpret_cast<uint2*>(g_Abf);
    const int base = blockIdx.x * 1024 + threadIdx.x;

    float4 v[4];
#pragma unroll
    for (int i = 0; i < 4; i++)
        v[i] = A4[base + i * 256];
#pragma unroll
    for (int i = 0; i < 4; i++) {
        uint2 o;
        o.x = bf2_bits(__floats2bfloat162_rn(v[i].x, v[i].y));
        o.y = bf2_bits(__floats2bfloat162_rn(v[i].z, v[i].w));
        O2[base + i * 256] = o;
    }
}

// ---------------- HMMA GEMM, CTA 256x128, warp grid 4x4, warp tile 64x32 ----------
// D = L @ B where B[k][n] = A[k][n] loaded via ldmatrix.trans (col-fragments).
// MODE 0: L = g_Abf ; H = 4D + I -> g_Hbf + row partials
// MODE 1: L = g_Hbf ; out = s_inv[r] * D (fp32), inv computed in prologue
template <int MODE>
__launch_bounds__(512, 1)
__global__ void gemm_mma(float* __restrict__ Cout)
{
    extern __shared__ char dyn_raw[];
    const uint32_t sb = smem_u32(dyn_raw);
    __shared__ float s_inv[BM];

    const int tid = threadIdx.x;
    const int lane = tid & 31;
    const int wid = tid >> 5;
    const int warp_m = wid & 3;
    const int warp_n = wid >> 2;
    const int row0 = blockIdx.y * BM;
    const int col0 = blockIdx.x * BN;

    const __nv_bfloat16* __restrict__ Lop = (MODE == 0) ? g_Abf : g_Hbf;
    const __nv_bfloat16* __restrict__ Rop = g_Abf;   // B = A k-rows, both modes

    // A fragments: non-trans, lane-constant offsets per k16 step
    uint32_t abase[2];
#pragma unroll
    for (int st = 0; st < 2; st++)
        abase[st] = swzA(warp_m * 64 + (lane & 15), st * 32 + ((lane >> 4) << 4));

    // B fragments: ldmatrix.x4.trans. Matrix m = lane>>3 maps to
    // (k-block = m&1, n-block = m>>1); lane row r = lane&7.
    uint32_t bbase[2][2];
    {
        const int m = lane >> 3, r = lane & 7;
#pragma unroll
        for (int st = 0; st < 2; st++)
#pragma unroll
            for (int np = 0; np < 2; np++)
                bbase[st][np] = swzB(st * 16 + ((m & 1) << 3) + r,
                                     warp_n * 4 + np * 2 + (m >> 1));
    }

    // fill k-tile kt into stage s: A 1024 chunks (2/thread) + B 512 (1/thread)
    auto fill = [&](int kt, int s) {
        const uint32_t ab = sb + s * A_STAGE;
        const uint32_t bb = sb + SMEM_B_OFF + s * B_STAGE;
#pragma unroll
        for (int i = 0; i < 2; i++) {
            const int ch = i * 512 + tid;
            const int row = ch >> 2, c16 = ch & 3;
            CP_ASYNC16(ab + swzA(row, c16 * 16),
                       Lop + (size_t)(row0 + row) * NMAT + kt * BK + c16 * 8);
        }
        {
            const int krow = tid >> 4, c = tid & 15;    // 32 k-rows x 16 chunks
            CP_ASYNC16(bb + swzB(krow, c),
                       Rop + (size_t)(kt * BK + krow) * NMAT + col0 + c * 8);
        }
    };

    float acc[4][4][4];
#pragma unroll
    for (int mt = 0; mt < 4; mt++)
#pragma unroll
        for (int nt = 0; nt < 4; nt++)
#pragma unroll
            for (int j = 0; j < 4; j++) acc[mt][nt][j] = 0.f;

    fill(0, 0); CP_COMMIT();
    fill(1, 1); CP_COMMIT();
    fill(2, 2); CP_COMMIT();

    // MODE 1: inv-degree for this CTA's rows, hidden under the prologue fills.
    if (MODE == 1 && tid < BM) {
        const int r = row0 + tid;
        float d = 0.f;
#pragma unroll
        for (int h = 0; h < 4; h++)
#pragma unroll
            for (int t = 0; t < NMAT / BN; t++) d += g_rowpart[h][t][r];
        if (d <= 1e-10f) d = 1.f;
        s_inv[tid] = 2.f / d;
    }
    // s_inv visibility: the mainloop's __syncthreads() (KT >= 1) orders it.

    for (int kt = 0; kt < KT; kt++) {
        CP_WAIT2();
        __syncthreads();
        const int s = kt & (STAGES - 1);
        const uint32_t ab = sb + s * A_STAGE;
        const uint32_t bb = sb + SMEM_B_OFF + s * B_STAGE;

        uint32_t a[4][4], b[2][4];

        // ---- step 0 ----
#pragma unroll
        for (int mt = 0; mt < 4; mt++)
            LDSM_X4(a[mt][0], a[mt][1], a[mt][2], a[mt][3], ab + abase[0] + mt * 1024);
#pragma unroll
        for (int np = 0; np < 2; np++)
            LDSM_X4T(b[np][0], b[np][1], b[np][2], b[np][3], bb + bbase[0][np]);

        const int f = kt + 3;
        if (f < KT) fill(f, f & (STAGES - 1));
        CP_COMMIT();

#pragma unroll
        for (int mt = 0; mt < 4; mt++)
#pragma unroll
            for (int nt = 0; nt < 4; nt++) {
                uint32_t bf[2] = {b[nt >> 1][(nt & 1) * 2], b[nt >> 1][(nt & 1) * 2 + 1]};
                MMA_BF16(acc[mt][nt], a[mt], bf);
            }

        // ---- step 1 ----
#pragma unroll
        for (int mt = 0; mt < 4; mt++)
            LDSM_X4(a[mt][0], a[mt][1], a[mt][2], a[mt][3], ab + abase[1] + mt * 1024);
#pragma unroll
        for (int np = 0; np < 2; np++)
            LDSM_X4T(b[np][0], b[np][1], b[np][2], b[np][3], bb + bbase[1][np]);
#pragma unroll
        for (int mt = 0; mt < 4; mt++)
#pragma unroll
            for (int nt = 0; nt < 4; nt++) {
                uint32_t bf[2] = {b[nt >> 1][(nt & 1) * 2], b[nt >> 1][(nt & 1) * 2 + 1]};
                MMA_BF16(acc[mt][nt], a[mt], bf);
            }
    }

    // ---------------- epilogue ----------------
#pragma unroll
    for (int mt = 0; mt < 4; mt++) {
        const int rA = row0 + warp_m * 64 + mt * 16 + (lane >> 2);
        const float s0 = (MODE == 0) ? 4.0f : s_inv[rA - row0];
        const float s1 = (MODE == 0) ? 4.0f : s_inv[rA + 8 - row0];
        float rs0 = 0.f, rs1 = 0.f;
#pragma unroll
        for (int nt = 0; nt < 4; nt++) {
            const int c = col0 + warp_n * 32 + nt * 8 + (lane & 3) * 2;
            float v0 = s0 * acc[mt][nt][0];
            float v1 = s0 * acc[mt][nt][1];
            float v2 = s1 * acc[mt][nt][2];
            float v3 = s1 * acc[mt][nt][3];
            if (MODE == 0) {
                if (rA == c)         v0 += 1.0f;
                if (rA == c + 1)     v1 += 1.0f;
                if (rA + 8 == c)     v2 += 1.0f;
                if (rA + 8 == c + 1) v3 += 1.0f;
                rs0 += v0 + v1;
                rs1 += v2 + v3;
                *reinterpret_cast<__nv_bfloat162*>(g_Hbf + (size_t)rA * NMAT + c) =
                    __floats2bfloat162_rn(v0, v1);
                *reinterpret_cast<__nv_bfloat162*>(g_Hbf + (size_t)(rA + 8) * NMAT + c) =
                    __floats2bfloat162_rn(v2, v3);
            } else {
                *reinterpret_cast<float2*>(Cout + (size_t)rA * NMAT + c) = make_float2(v0, v1);
                *reinterpret_cast<float2*>(Cout + (size_t)(rA + 8) * NMAT + c) = make_float2(v2, v3);
            }
        }
        if (MODE == 0) {
            rs0 += __shfl_xor_sync(0xFFFFFFFF, rs0, 1);
            rs0 += __shfl_xor_sync(0xFFFFFFFF, rs0, 2);
            rs1 += __shfl_xor_sync(0xFFFFFFFF, rs1, 1);
            rs1 += __shfl_xor_sync(0xFFFFFFFF, rs1, 2);
            if ((lane & 3) == 0) {
                g_rowpart[warp_n][blockIdx.x][rA] = rs0;
                g_rowpart[warp_n][blockIdx.x][rA + 8] = rs1;
            }
        }
    }
}

extern "C" void kernel_launch(void* const* d_in, const int* in_sizes, int n_in,
                              void* d_out, int out_size)
{
    const float* A = (const float*)d_in[0];   // weights unused: softmax over singleton == 1
    float* out = (float*)d_out;

    cudaFuncSetAttribute(gemm_mma<0>, cudaFuncAttributeMaxDynamicSharedMemorySize, SMEM_DYN);
    cudaFuncSetAttribute(gemm_mma<1>, cudaFuncAttributeMaxDynamicSharedMemorySize, SMEM_DYN);

    convert_kernel<<<NMAT * NMAT / 4096, 256>>>(A);
    gemm_mma<0><<<dim3(NMAT / BN, NMAT / BM), 512, SMEM_DYN>>>(out);   // H = 4*A@A + I
    gemm_mma<1><<<dim3(NMAT / BN, NMAT / BM), 512, SMEM_DYN>>>(out);   // out = diag(2/deg)@(H@A)
}